// round 1
// baseline (speedup 1.0000x reference)
#include <cuda_runtime.h>
#include <cstdint>

#define DIMD 1024
#define NB   8
#define SQ   2048
#define SKV  2048

// ---- scratch (device globals; no allocation allowed) ----
__device__ float g_Xr[(size_t)NB * SQ * DIMD];     // tf32-rounded x
__device__ float g_Cr[(size_t)NB * SKV * DIMD];    // tf32-rounded context
__device__ float g_Wqr[DIMD * DIMD];
__device__ float g_Wkr[DIMD * DIMD];
__device__ float g_Wvr[DIMD * DIMD];
__device__ float g_Q[(size_t)NB * SQ * DIMD];      // tf32-rounded Q
__device__ float g_K[(size_t)NB * SKV * DIMD];     // tf32-rounded K
__device__ float g_Vt[(size_t)NB * DIMD * SKV];    // tf32-rounded V^T  [b][e][t]
__device__ float g_S[(size_t)NB * SQ * SKV];       // logits, then P (tf32-rounded)

__device__ __forceinline__ float tf32r(float v) {
    asm("cvt.rna.tf32.f32 %0, %1;" : "=f"(v) : "f"(v));
    return v;
}

// ---- round fp32 -> tf32 (stored as fp32) ----
__global__ void round_tf32_kernel(const float4* __restrict__ in, float4* __restrict__ out, int n4) {
    int i = blockIdx.x * blockDim.x + threadIdx.x;
    int stride = gridDim.x * blockDim.x;
    for (; i < n4; i += stride) {
        float4 v = in[i];
        v.x = tf32r(v.x); v.y = tf32r(v.y); v.z = tf32r(v.z); v.w = tf32r(v.w);
        out[i] = v;
    }
}

// ---- TN GEMM: C[M,N] = alpha * A[M,K] * B[N,K]^T, tf32 mma, fp32 accum ----
#define BM 128
#define BN 128
#define BK 16
#define SSTR 20   // 16 + 4 pad (floats)

__device__ __forceinline__ void cpa16(uint32_t s, const void* g) {
    asm volatile("cp.async.cg.shared.global [%0], [%1], 16;" :: "r"(s), "l"(g));
}

// MODE 0: fp32 store; MODE 1: tf32-rounded store; MODE 2: tf32-rounded transposed store C[n*ldc+m]
template<int MODE>
__global__ __launch_bounds__(256)
void gemm_tn(const float* __restrict__ Ag, const float* __restrict__ Bg, float* __restrict__ Cg,
             int M, int N, int K, long sA, long sB, long sC, int ldc, float alpha)
{
    __shared__ __align__(16) float As[2][BM * SSTR];
    __shared__ __align__(16) float Bs[2][BN * SSTR];
    const float* A  = Ag + (long)blockIdx.z * sA;
    const float* Bp = Bg + (long)blockIdx.z * sB;
    float*       C  = Cg + (long)blockIdx.z * sC;
    const int m0 = blockIdx.y * BM, n0 = blockIdx.x * BN;
    const int tid = threadIdx.x, lane = tid & 31, warp = tid >> 5;
    const int wm = (warp & 1) * 64, wn = (warp >> 1) * 32;

    const int lr = tid >> 2;        // 0..63
    const int lc = (tid & 3) * 4;   // 0,4,8,12

    uint32_t sA0 = (uint32_t)__cvta_generic_to_shared(&As[0][0]);
    uint32_t sB0 = (uint32_t)__cvta_generic_to_shared(&Bs[0][0]);
    const uint32_t bufSz = BM * SSTR * 4;

    float acc[4][4][4];
    #pragma unroll
    for (int i = 0; i < 4; i++)
        #pragma unroll
        for (int j = 0; j < 4; j++)
            #pragma unroll
            for (int r = 0; r < 4; r++) acc[i][j][r] = 0.f;

    const float* aRow0 = A  + (long)(m0 + lr)      * K + lc;
    const float* aRow1 = A  + (long)(m0 + lr + 64) * K + lc;
    const float* bRow0 = Bp + (long)(n0 + lr)      * K + lc;
    const float* bRow1 = Bp + (long)(n0 + lr + 64) * K + lc;
    uint32_t saw0 = sA0 + (uint32_t)((lr      * SSTR + lc) * 4);
    uint32_t saw1 = sA0 + (uint32_t)(((lr+64) * SSTR + lc) * 4);
    uint32_t sbw0 = sB0 + (uint32_t)((lr      * SSTR + lc) * 4);
    uint32_t sbw1 = sB0 + (uint32_t)(((lr+64) * SSTR + lc) * 4);

    auto issue = [&](int kt, int buf) {
        int ko = kt * BK;
        uint32_t off = (uint32_t)buf * bufSz;
        cpa16(saw0 + off, aRow0 + ko);
        cpa16(saw1 + off, aRow1 + ko);
        cpa16(sbw0 + off, bRow0 + ko);
        cpa16(sbw1 + off, bRow1 + ko);
        asm volatile("cp.async.commit_group;");
    };

    // ldmatrix address components (non-trans for both A and B; tf32 frag layouts)
    const int arow = wm + (lane & 7) + ((lane >> 3) & 1) * 8;
    const int acol = ((lane >> 4) & 1) * 4;
    const int brow = wn + (lane & 7);
    const int bcol = (((lane & 15) >> 3) & 1) * 4;

    const int Kt = K / BK;
    issue(0, 0);
    for (int kt = 0; kt < Kt; ++kt) {
        int buf = kt & 1;
        if (kt + 1 < Kt) {
            issue(kt + 1, buf ^ 1);
            asm volatile("cp.async.wait_group 1;");
        } else {
            asm volatile("cp.async.wait_group 0;");
        }
        __syncthreads();
        uint32_t aBase = sA0 + (uint32_t)buf * bufSz;
        uint32_t bBase = sB0 + (uint32_t)buf * bufSz;
        #pragma unroll
        for (int ks = 0; ks < BK; ks += 8) {
            uint32_t a[4][4];
            #pragma unroll
            for (int mt = 0; mt < 4; mt++) {
                uint32_t addr = aBase + (uint32_t)(((arow + mt * 16) * SSTR + ks + acol) * 4);
                asm volatile("ldmatrix.sync.aligned.m8n8.x4.shared.b16 {%0,%1,%2,%3}, [%4];"
                    : "=r"(a[mt][0]), "=r"(a[mt][1]), "=r"(a[mt][2]), "=r"(a[mt][3]) : "r"(addr));
            }
            uint32_t b[4][2];
            #pragma unroll
            for (int nt = 0; nt < 4; nt++) {
                uint32_t addr = bBase + (uint32_t)(((brow + nt * 8) * SSTR + ks + bcol) * 4);
                asm volatile("ldmatrix.sync.aligned.m8n8.x2.shared.b16 {%0,%1}, [%2];"
                    : "=r"(b[nt][0]), "=r"(b[nt][1]) : "r"(addr));
            }
            #pragma unroll
            for (int mt = 0; mt < 4; mt++)
                #pragma unroll
                for (int nt = 0; nt < 4; nt++) {
                    asm volatile("mma.sync.aligned.m16n8k8.row.col.f32.tf32.tf32.f32 "
                        "{%0,%1,%2,%3}, {%4,%5,%6,%7}, {%8,%9}, {%0,%1,%2,%3};"
                        : "+f"(acc[mt][nt][0]), "+f"(acc[mt][nt][1]),
                          "+f"(acc[mt][nt][2]), "+f"(acc[mt][nt][3])
                        : "r"(a[mt][0]), "r"(a[mt][1]), "r"(a[mt][2]), "r"(a[mt][3]),
                          "r"(b[nt][0]), "r"(b[nt][1]));
                }
        }
        __syncthreads();
    }

    // epilogue
    const int rr = lane >> 2, cc = (lane & 3) * 2;
    #pragma unroll
    for (int mt = 0; mt < 4; mt++) {
        #pragma unroll
        for (int nt = 0; nt < 4; nt++) {
            int row = m0 + wm + mt * 16 + rr;
            int col = n0 + wn + nt * 8 + cc;
            float v0 = acc[mt][nt][0] * alpha, v1 = acc[mt][nt][1] * alpha;
            float v2 = acc[mt][nt][2] * alpha, v3 = acc[mt][nt][3] * alpha;
            if (MODE >= 1) { v0 = tf32r(v0); v1 = tf32r(v1); v2 = tf32r(v2); v3 = tf32r(v3); }
            if (MODE == 2) {
                C[(long)col       * ldc + row    ] = v0;
                C[(long)(col + 1) * ldc + row    ] = v1;
                C[(long)col       * ldc + row + 8] = v2;
                C[(long)(col + 1) * ldc + row + 8] = v3;
            } else {
                *reinterpret_cast<float2*>(&C[(long)row       * ldc + col]) = make_float2(v0, v1);
                *reinterpret_cast<float2*>(&C[(long)(row + 8) * ldc + col]) = make_float2(v2, v3);
            }
        }
    }
}

// ---- in-place row softmax over 2048 cols, output tf32-rounded ----
__global__ void softmax_kernel(float* __restrict__ S) {
    float* p = S + (long)blockIdx.x * SKV;
    const int tid = threadIdx.x;  // 256
    float v[8];
    float mx = -3.4e38f;
    #pragma unroll
    for (int i = 0; i < 8; i++) { v[i] = p[tid + (i << 8)]; mx = fmaxf(mx, v[i]); }
    #pragma unroll
    for (int o = 16; o; o >>= 1) mx = fmaxf(mx, __shfl_xor_sync(0xffffffffu, mx, o));
    __shared__ float red[8];
    if ((tid & 31) == 0) red[tid >> 5] = mx;
    __syncthreads();
    float m = red[0];
    #pragma unroll
    for (int i = 1; i < 8; i++) m = fmaxf(m, red[i]);
    float s = 0.f;
    #pragma unroll
    for (int i = 0; i < 8; i++) { v[i] = __expf(v[i] - m); s += v[i]; }
    #pragma unroll
    for (int o = 16; o; o >>= 1) s += __shfl_xor_sync(0xffffffffu, s, o);
    __syncthreads();
    if ((tid & 31) == 0) red[tid >> 5] = s;
    __syncthreads();
    float tot = 0.f;
    #pragma unroll
    for (int i = 0; i < 8; i++) tot += red[i];
    float inv = 1.0f / tot;
    #pragma unroll
    for (int i = 0; i < 8; i++) p[tid + (i << 8)] = tf32r(v[i] * inv);
}

extern "C" void kernel_launch(void* const* d_in, const int* in_sizes, int n_in,
                              void* d_out, int out_size) {
    const float* x  = (const float*)d_in[0];
    const float* cx = (const float*)d_in[1];
    const float* wq = (const float*)d_in[2];
    const float* wk = (const float*)d_in[3];
    const float* wv = (const float*)d_in[4];
    float* out = (float*)d_out;

    float *pXr, *pCr, *pWq, *pWk, *pWv, *pQ, *pK, *pVt, *pS;
    cudaGetSymbolAddress((void**)&pXr, g_Xr);
    cudaGetSymbolAddress((void**)&pCr, g_Cr);
    cudaGetSymbolAddress((void**)&pWq, g_Wqr);
    cudaGetSymbolAddress((void**)&pWk, g_Wkr);
    cudaGetSymbolAddress((void**)&pWv, g_Wvr);
    cudaGetSymbolAddress((void**)&pQ,  g_Q);
    cudaGetSymbolAddress((void**)&pK,  g_K);
    cudaGetSymbolAddress((void**)&pVt, g_Vt);
    cudaGetSymbolAddress((void**)&pS,  g_S);

    // 1) round inputs to tf32
    round_tf32_kernel<<<2048, 256>>>((const float4*)x,  (float4*)pXr, NB * SQ * DIMD / 4);
    round_tf32_kernel<<<2048, 256>>>((const float4*)cx, (float4*)pCr, NB * SKV * DIMD / 4);
    round_tf32_kernel<<<512,  256>>>((const float4*)wq, (float4*)pWq, DIMD * DIMD / 4);
    round_tf32_kernel<<<512,  256>>>((const float4*)wk, (float4*)pWk, DIMD * DIMD / 4);
    round_tf32_kernel<<<512,  256>>>((const float4*)wv, (float4*)pWv, DIMD * DIMD / 4);

    dim3 blk(256);
    // 2) Q = X Wq^T   (tf32-rounded store)
    gemm_tn<1><<<dim3(DIMD / BN, NB * SQ / BM, 1), blk>>>(
        pXr, pWq, pQ, NB * SQ, DIMD, DIMD, 0, 0, 0, DIMD, 1.f);
    // 3) K = C Wk^T
    gemm_tn<1><<<dim3(DIMD / BN, NB * SKV / BM, 1), blk>>>(
        pCr, pWk, pK, NB * SKV, DIMD, DIMD, 0, 0, 0, DIMD, 1.f);
    // 4) Vt[b][e][t] = (C Wv^T)^T   (transposed tf32 store, batched)
    gemm_tn<2><<<dim3(DIMD / BN, SKV / BM, NB), blk>>>(
        pCr, pWv, pVt, SKV, DIMD, DIMD,
        (long)SKV * DIMD, 0, (long)DIMD * SKV, SKV, 1.f);
    // 5) S[b] = Q[b] K[b]^T * D^-0.5
    gemm_tn<0><<<dim3(SKV / BN, SQ / BM, NB), blk>>>(
        pQ, pK, pS, SQ, SKV, DIMD,
        (long)SQ * DIMD, (long)SKV * DIMD, (long)SQ * SKV, SKV, 0.03125f);
    // 6) P = softmax(S)  (in place, tf32-rounded)
    softmax_kernel<<<NB * SQ, 256>>>(pS);
    // 7) O[b] = P[b] Vt[b]^T  -> d_out (fp32)
    gemm_tn<0><<<dim3(DIMD / BN, SQ / BM, NB), blk>>>(
        pS, pVt, out, SQ, DIMD, SKV,
        (long)SQ * SKV, (long)DIMD * SKV, (long)SQ * DIMD, DIMD, 1.f);
}